// round 1
// baseline (speedup 1.0000x reference)
#include <cuda_runtime.h>
#include <cstdint>

// ---------------------------------------------------------------------------
// GRUConv3d: 8 directions x (conv3d h,z,s gates) -> diagonal GRU scan -> sum
// Sizes: B=2, Cin=Cout=32, D=H=W=32, 3x3x3 taps, padding 1.
// Plan: one fused fp32 conv kernel (FFMA2 / fma.rn.f32x2 packed math) writes
// hb, sigmoid(z), sigmoid(s) for all 8 dirs to scratch; then 8 scan kernels
// walk the (1,1,1)-diagonal chains in the flipped frame with flips folded
// into the index map, accumulating out += h * s.
// ---------------------------------------------------------------------------

#define NB   2
#define NC   32
#define ND   32
#define NSP  (32*32*32)          // 32768 spatial
#define NDIR 8

// scratch: [dir][gate(0=hb,1=z,2=s)][b][c][spatial]  = 201 MB
__device__ float g_buf[NDIR * 3 * NB * NC * NSP];

// ---------------- packed f32x2 helpers -------------------------------------
__device__ __forceinline__ unsigned long long pack2(float v) {
    unsigned long long r;
    asm("mov.b64 %0, {%1, %1};" : "=l"(r) : "r"(__float_as_uint(v)));
    return r;
}
__device__ __forceinline__ unsigned long long packab(float a, float b) {
    unsigned long long r;
    asm("mov.b64 %0, {%1, %2};" : "=l"(r) : "r"(__float_as_uint(a)), "r"(__float_as_uint(b)));
    return r;
}
__device__ __forceinline__ void ffma2(unsigned long long& acc,
                                      unsigned long long a, unsigned long long b) {
    asm("fma.rn.f32x2 %0, %1, %2, %0;" : "+l"(acc) : "l"(a), "l"(b));
}

// ---------------- conv kernel ----------------------------------------------
// Block: 256 threads. Computes all 96 couts (3 gates x 32) for a spatial tile
// of (Dt=2, Ht=2, Wt=32) for one (b, dir).
// Warp w (0..7) owns couts [12w, 12w+12); lanes = w-coordinate.
// Per-thread: 6 co-pairs x 4 spatial f32x2 accumulators (48 fp32).
// smem: x halo tile [8ci][4][4][34] + weights [8ci][27tap][96co padded to 98].

#define CIN_CHUNK 8
#define XS_ELEMS  (CIN_CHUNK*4*4*34)            // 4352
#define WS_STRIDE 98                            // even pad: 8B-aligned LDS.64, low conflicts
#define WS_ELEMS  (CIN_CHUNK*27*WS_STRIDE)      // 21168
#define CONV_SMEM ((XS_ELEMS + WS_ELEMS) * 4)   // 102080 bytes

__global__ void __launch_bounds__(256, 2)
conv_kernel(const float* __restrict__ x,
            const float* __restrict__ Wh, const float* __restrict__ bh,
            const float* __restrict__ Wz, const float* __restrict__ bz,
            const float* __restrict__ Ws, const float* __restrict__ bs)
{
    extern __shared__ float sm[];
    float* xs = sm;                 // [8][4][4][34]
    float* ws = sm + XS_ELEMS;      // [8][27][98]
    __shared__ float bsm[96];

    const int tid  = threadIdx.x;
    const int lane = tid & 31;
    const int wid  = tid >> 5;          // 0..7
    const int b    = blockIdx.y;
    const int n    = blockIdx.z;        // direction
    const int d0   = (blockIdx.x >> 4) * 2;
    const int h0   = (blockIdx.x & 15) * 2;

    if (tid < 96) {
        int g = tid / 32, co = tid & 31;
        const float* bp = (g == 0) ? bh : ((g == 1) ? bz : bs);
        bsm[tid] = bp[n * 32 + co];
    }
    __syncthreads();

    // accumulators: [co-pair 6][dd 2][dh 2], init with bias pair
    unsigned long long acc[6][2][2];
#pragma unroll
    for (int cop = 0; cop < 6; ++cop) {
        int cg = wid * 12 + cop * 2;
        unsigned long long bb = packab(bsm[cg], bsm[cg + 1]);
#pragma unroll
        for (int dd = 0; dd < 2; ++dd)
#pragma unroll
            for (int dh = 0; dh < 2; ++dh)
                acc[cop][dd][dh] = bb;
    }

    for (int cc = 0; cc < 4; ++cc) {        // 4 chunks of 8 input channels
        const int ci0 = cc * CIN_CHUNK;

        // --- load x halo tile (zero-padded boundary) ---
        for (int idx = tid; idx < XS_ELEMS; idx += 256) {
            int w_ = idx % 34;
            int r  = idx / 34;
            int h_ = r % 4;  r /= 4;
            int d_ = r % 4;
            int ci = r / 4;
            int gd = d0 - 1 + d_, gh = h0 - 1 + h_, gw = w_ - 1;
            float v = 0.f;
            if (gd >= 0 && gd < 32 && gh >= 0 && gh < 32 && gw >= 0 && gw < 32)
                v = x[(((b * NC + ci0 + ci) * 32 + gd) * 32 + gh) * 32 + gw];
            xs[((ci * 4 + d_) * 4 + h_) * 34 + w_] = v;
        }
        // --- load weights [ci][tap][co_g] (co_g fastest, stride 98) ---
        for (int idx = tid; idx < 96 * CIN_CHUNK * 27; idx += 256) {
            int t   = idx % 27;
            int r   = idx / 27;
            int ci  = r % CIN_CHUNK;
            int cg  = r / CIN_CHUNK;       // 0..95
            int g   = cg >> 5;
            int co  = cg & 31;
            const float* Wp = (g == 0) ? Wh : ((g == 1) ? Wz : Ws);
            ws[(ci * 27 + t) * WS_STRIDE + cg] =
                Wp[((n * 32 + co) * 32 + (ci0 + ci)) * 27 + t];
        }
        __syncthreads();

        // --- compute ---
        for (int ci = 0; ci < CIN_CHUNK; ++ci) {
            const float* xrow = xs + ci * (4 * 4 * 34) + lane;
            const float* wci  = ws + ci * 27 * WS_STRIDE + wid * 12;
#pragma unroll
            for (int td = 0; td < 3; ++td) {
#pragma unroll
                for (int th = 0; th < 3; ++th) {
#pragma unroll
                    for (int tw = 0; tw < 3; ++tw) {
                        const int t = (td * 3 + th) * 3 + tw;
                        unsigned long long xx[2][2];
#pragma unroll
                        for (int dd = 0; dd < 2; ++dd)
#pragma unroll
                            for (int dh = 0; dh < 2; ++dh)
                                xx[dd][dh] = pack2(xrow[((dd + td) * 4 + (dh + th)) * 34 + tw]);
                        const float* wrow = wci + t * WS_STRIDE;
#pragma unroll
                        for (int cop = 0; cop < 6; ++cop) {
                            unsigned long long wp =
                                *reinterpret_cast<const unsigned long long*>(wrow + cop * 2);
#pragma unroll
                            for (int dd = 0; dd < 2; ++dd)
#pragma unroll
                                for (int dh = 0; dh < 2; ++dh)
                                    ffma2(acc[cop][dd][dh], xx[dd][dh], wp);
                        }
                    }
                }
            }
        }
        __syncthreads();
    }

    // --- epilogue: sigmoid for z,s gates; write to scratch ---
#pragma unroll
    for (int cop = 0; cop < 6; ++cop) {
#pragma unroll
        for (int s = 0; s < 2; ++s) {
            int cg = wid * 12 + cop * 2 + s;
            int g  = cg >> 5;
            int co = cg & 31;
            float* base = g_buf + (size_t)(((n * 3 + g) * NB + b) * NC + co) * NSP;
#pragma unroll
            for (int dd = 0; dd < 2; ++dd)
#pragma unroll
                for (int dh = 0; dh < 2; ++dh) {
                    unsigned long long a = acc[cop][dd][dh];
                    float v = (s == 0)
                        ? __uint_as_float((unsigned)(a & 0xffffffffull))
                        : __uint_as_float((unsigned)(a >> 32));
                    if (g != 0) v = 1.f / (1.f + __expf(-v));
                    base[(d0 + dd) * 1024 + (h0 + dh) * 32 + lane] = v;
                }
        }
    }
}

// ---------------- scan kernel ----------------------------------------------
// One launch per direction n. Chains along the (1,1,1) diagonal in the
// flipped frame: invariants delta1 = i_f - j_f, delta2 = i_f - k_f.
// Warp = (b, c, delta1, half); lanes cover 32 consecutive delta2 -> at every
// step active lanes hit 32 consecutive w addresses (coalesced).
// O = z*hb + (1-z)*prev, prev = h0 on first active step.

__global__ void scan_kernel(const float* __restrict__ h0v,
                            float* __restrict__ out, int n, int first)
{
    const int gwarp = (blockIdx.x * blockDim.x + threadIdx.x) >> 5;
    const int lane  = threadIdx.x & 31;
    const int half  = gwarp & 1;
    const int d1i   = (gwarp >> 1) % 63;
    const int c     = (gwarp / 126) % NC;
    const int b     = gwarp / (126 * NC);
    if (b >= NB) return;

    const int delta1 = d1i - 31;
    const int delta2 = half * 32 + lane - 31;     // [-31, 32]
    const bool lane_ok = (delta2 <= 31);

    const int di = (n & 4) ? 1 : -1;
    const int dj = (n & 2) ? 1 : -1;
    const int dk = (n & 1) ? 1 : -1;

    const float* hbp = g_buf + (size_t)(((n * 3 + 0) * NB + b) * NC + c) * NSP;
    const float* zp  = g_buf + (size_t)(((n * 3 + 1) * NB + b) * NC + c) * NSP;
    const float* sp  = g_buf + (size_t)(((n * 3 + 2) * NB + b) * NC + c) * NSP;
    float* op = out + (size_t)(b * NC + c) * NSP;

    float h = h0v[n * 32 + c];

    for (int m = 0; m < 32; ++m) {
        int jf = m - delta1;
        if (jf < 0) continue;      // uniform across warp
        if (jf > 31) break;        // uniform across warp
        int kf = m - delta2;
        bool act = lane_ok && (kf >= 0) && (kf <= 31);
        int i = (di > 0) ? m  : 31 - m;
        int j = (dj > 0) ? jf : 31 - jf;
        int k = (dk > 0) ? kf : 31 - kf;
        int idx = i * 1024 + j * 32 + k;
        if (act) {
            float z  = zp[idx];
            float hb = hbp[idx];
            h = z * hb + (1.f - z) * h;
            float contrib = h * sp[idx];
            if (first) op[idx] = contrib;
            else       op[idx] += contrib;
        }
    }
}

// ---------------- launch ----------------------------------------------------
extern "C" void kernel_launch(void* const* d_in, const int* in_sizes, int n_in,
                              void* d_out, int out_size)
{
    const float* x   = (const float*)d_in[0];
    const float* Wh  = (const float*)d_in[1];
    const float* bh  = (const float*)d_in[2];
    const float* Wz  = (const float*)d_in[3];
    const float* bz  = (const float*)d_in[4];
    const float* Ws  = (const float*)d_in[5];
    const float* bs  = (const float*)d_in[6];
    const float* h0v = (const float*)d_in[7];
    float* out = (float*)d_out;

    cudaFuncSetAttribute(conv_kernel,
                         cudaFuncAttributeMaxDynamicSharedMemorySize, CONV_SMEM);

    // fused conv for all 8 dirs: grid (16*16 spatial tiles, B, dirs)
    conv_kernel<<<dim3(256, NB, NDIR), 256, CONV_SMEM>>>(x, Wh, bh, Wz, bz, Ws, bs);

    // 8 sequential directional scans; dir 0 initializes out
    const int warps = NB * NC * 63 * 2;          // 8064
    const int blocks = (warps + 7) / 8;          // 1008 (256 thr = 8 warps)
    for (int n = 0; n < NDIR; ++n)
        scan_kernel<<<blocks, 256>>>(h0v, out, n, n == 0);
}

// round 3
// speedup vs baseline: 2.0354x; 2.0354x over previous
#include <cuda_runtime.h>
#include <cuda_bf16.h>
#include <cstdint>

// ===========================================================================
// GRUConv3d via one big HMMA GEMM (base-ISA mma.sync, valid at sm_103 target):
//  1) wprep: W -> bf16 hi/lo K-major [768][864], bias[768]
//  2) im2col: x -> bf16 hi/lo K-major [65536][864]  (K = ci*27 + tap)
//  3) GEMM: C[768][65536] fp32 = 3-term bf16 split (hi*hi + lo*hi + hi*lo)
//  4) scan: 8 dirs, sigmoid on the fly, contrib written into hb plane
//  5) reduce: out = sum over dirs
// ===========================================================================

#define NB 2
#define NSP 32768
#define NROW 65536
#define KDIM 864            // 32ci * 27taps = 54 * 16
#define MTOT 768            // 8 dir * 3 gate * 32 co

__device__ __align__(16) __nv_bfloat16 g_Bhi[(size_t)NROW * KDIM];
__device__ __align__(16) __nv_bfloat16 g_Blo[(size_t)NROW * KDIM];
__device__ __align__(16) __nv_bfloat16 g_Whi[(size_t)MTOT * KDIM];
__device__ __align__(16) __nv_bfloat16 g_Wlo[(size_t)MTOT * KDIM];
__device__ __align__(16) float         g_C[(size_t)MTOT * NROW];
__device__ float                       g_bias[MTOT];

// ---------------- helpers ---------------------------------------------------
__device__ __forceinline__ uint32_t smem_u32(const void* p) {
    uint32_t a;
    asm("{ .reg .u64 t; cvta.to.shared.u64 t, %1; cvt.u32.u64 %0, t; }" : "=r"(a) : "l"(p));
    return a;
}
__device__ __forceinline__ void cp16(uint32_t dst, const void* src) {
    asm volatile("cp.async.cg.shared.global [%0], [%1], 16;" :: "r"(dst), "l"(src));
}
#define CP_COMMIT() asm volatile("cp.async.commit_group;" ::: "memory")
#define CP_WAIT(n)  asm volatile("cp.async.wait_group %0;" :: "n"(n) : "memory")

#define LDSM4(r, a) \
    asm volatile("ldmatrix.sync.aligned.m8n8.x4.shared.b16 {%0,%1,%2,%3}, [%4];" \
                 : "=r"((r)[0]), "=r"((r)[1]), "=r"((r)[2]), "=r"((r)[3]) : "r"(a))

#define MMA16816(c, a, b0, b1) \
    asm volatile("mma.sync.aligned.m16n8k16.row.col.f32.bf16.bf16.f32 " \
                 "{%0,%1,%2,%3}, {%4,%5,%6,%7}, {%8,%9}, {%0,%1,%2,%3};" \
                 : "+f"((c)[0]), "+f"((c)[1]), "+f"((c)[2]), "+f"((c)[3]) \
                 : "r"((a)[0]), "r"((a)[1]), "r"((a)[2]), "r"((a)[3]), \
                   "r"(b0), "r"(b1))

__device__ __forceinline__ void split_bf16(float v, __nv_bfloat16& hi, __nv_bfloat16& lo) {
    hi = __float2bfloat16(v);
    lo = __float2bfloat16(v - __bfloat162float(hi));
}

// ---------------- 1) weight prep --------------------------------------------
__global__ void wprep_kernel(const float* __restrict__ Wh, const float* __restrict__ bh,
                             const float* __restrict__ Wz, const float* __restrict__ bz,
                             const float* __restrict__ Ws, const float* __restrict__ bs)
{
    const int m = blockIdx.x;
    const int n = m / 96, r = m % 96, g = r >> 5, co = r & 31;
    const float* Wp = (g == 0) ? Wh : ((g == 1) ? Wz : Ws);
    const float* bp = (g == 0) ? bh : ((g == 1) ? bz : bs);
    if (threadIdx.x == 0) g_bias[m] = bp[n * 32 + co];
    for (int k = threadIdx.x; k < KDIM; k += blockDim.x) {
        int ci = k / 27, t = k % 27;
        float v = Wp[((n * 32 + co) * 32 + ci) * 27 + t];
        __nv_bfloat16 hi, lo; split_bf16(v, hi, lo);
        g_Whi[(size_t)m * KDIM + k] = hi;
        g_Wlo[(size_t)m * KDIM + k] = lo;
    }
}

// ---------------- 2) im2col --------------------------------------------------
#define I2C_STRIDE 898                      // bf16 elems; 898*2/4=449 -> conflict-free
#define I2C_SMEM (2 * 32 * I2C_STRIDE * 2)  // hi + lo tiles
__global__ void __launch_bounds__(256)
im2col_kernel(const float* __restrict__ x)
{
    extern __shared__ __nv_bfloat16 sm2[];
    __nv_bfloat16* shi = sm2;
    __nv_bfloat16* slo = sm2 + 32 * I2C_STRIDE;

    const int tid = threadIdx.x, lane = tid & 31, wi = tid >> 5;
    const int bid = blockIdx.x;
    const int b = bid >> 10, d = (bid >> 5) & 31, h = bid & 31;

    for (int k = wi; k < KDIM; k += 8) {
        int ci = k / 27, t = k % 27;
        int td = t / 9, th = (t % 9) / 3, tw = t % 3;
        int gd = d + td - 1, gh = h + th - 1, gw = lane + tw - 1;
        float v = 0.f;
        if (gd >= 0 && gd < 32 && gh >= 0 && gh < 32 && gw >= 0 && gw < 32)
            v = x[(((b * 32 + ci) * 32 + gd) * 32 + gh) * 32 + gw];
        __nv_bfloat16 hi, lo; split_bf16(v, hi, lo);
        shi[lane * I2C_STRIDE + k] = hi;
        slo[lane * I2C_STRIDE + k] = lo;
    }
    __syncthreads();

    const size_t row0 = (size_t)b * NSP + d * 1024 + h * 32;
    const uint32_t* shiw = (const uint32_t*)shi;
    const uint32_t* slow = (const uint32_t*)slo;
    uint32_t* ghi = (uint32_t*)(g_Bhi + row0 * KDIM);
    uint32_t* glo = (uint32_t*)(g_Blo + row0 * KDIM);
    const int KW = KDIM / 2;                 // 432 words per row
    for (int idx = tid; idx < 32 * KW; idx += 256) {
        int w = idx / KW, kw = idx % KW;
        ghi[(size_t)w * KW + kw] = shiw[w * (I2C_STRIDE / 2) + kw];
        glo[(size_t)w * KW + kw] = slow[w * (I2C_STRIDE / 2) + kw];
    }
}

// ---------------- 3) GEMM (HMMA, 128x128 tile, K chunks of 32) ---------------
// smem stage: Ah[128][40] Al Bh Bl, row stride 80B (conflict-free ldmatrix)
#define ASTR_B 80
#define REG_A 0
#define REG_AL 10240
#define REG_B 20480
#define REG_BL 30720
#define STAGE_B 40960
#define GEMM_SMEM (2 * STAGE_B)
#define NKC (KDIM / 32)                     // 27

__global__ void __launch_bounds__(256, 1)
gemm_kernel()
{
    extern __shared__ __align__(16) char sm[];
    const int tid = threadIdx.x, lane = tid & 31, wid = tid >> 5;
    const int m0 = blockIdx.x * 128;
    const size_t n0 = (size_t)blockIdx.y * 128;
    const int wm = wid & 3, wn = wid >> 2;
    const uint32_t sbase = smem_u32(sm);

    const char* gAh = (const char*)g_Whi + (size_t)m0 * (KDIM * 2);
    const char* gAl = (const char*)g_Wlo + (size_t)m0 * (KDIM * 2);
    const char* gBh = (const char*)g_Bhi + n0 * (KDIM * 2);
    const char* gBl = (const char*)g_Blo + n0 * (KDIM * 2);

    float acc[2][8][4];
#pragma unroll
    for (int i = 0; i < 2; ++i)
#pragma unroll
        for (int j = 0; j < 8; ++j)
#pragma unroll
            for (int q = 0; q < 4; ++q) acc[i][j][q] = 0.f;

    // ldmatrix per-lane offsets
    const int a_row = lane & 15;
    const int a_k8  = (lane >> 4) << 3;                       // 0 or 8 (bf16 elems)
    const int b_row = wn * 64 + (lane & 7) + ((lane >> 4) << 3);
    const int b_k8  = ((lane >> 3) & 1) << 3;

    auto load_stage = [&](int kc, int s) {
        const int koff = kc * 64;                              // bytes
        const uint32_t st = sbase + s * STAGE_B;
        for (int i = tid; i < 512; i += 256) {
            int r = i >> 2, c = (i & 3) << 4;
            uint32_t d = st + r * ASTR_B + c;
            size_t go = (size_t)r * (KDIM * 2) + koff + c;
            cp16(d + REG_A,  gAh + go);
            cp16(d + REG_AL, gAl + go);
            cp16(d + REG_B,  gBh + go);
            cp16(d + REG_BL, gBl + go);
        }
        CP_COMMIT();
    };

    auto compute = [&](int s) {
        const uint32_t st = sbase + s * STAGE_B;
#pragma unroll
        for (int ks = 0; ks < 2; ++ks) {
            uint32_t Ah[2][4], Al[2][4], Bh[4][4], Bl[4][4];
#pragma unroll
            for (int mt2 = 0; mt2 < 2; ++mt2) {
                uint32_t a = st + (wm * 32 + mt2 * 16 + a_row) * ASTR_B
                               + (ks * 16 + a_k8) * 2;
                LDSM4(Ah[mt2], a + REG_A);
                LDSM4(Al[mt2], a + REG_AL);
            }
#pragma unroll
            for (int bt = 0; bt < 4; ++bt) {
                uint32_t a = st + (b_row + bt * 16) * ASTR_B
                               + (ks * 16 + b_k8) * 2;
                LDSM4(Bh[bt], a + REG_B);
                LDSM4(Bl[bt], a + REG_BL);
            }
#pragma unroll
            for (int mt2 = 0; mt2 < 2; ++mt2)
#pragma unroll
                for (int nt8 = 0; nt8 < 8; ++nt8) {
                    const uint32_t* bh = &Bh[nt8 >> 1][(nt8 & 1) * 2];
                    const uint32_t* bl = &Bl[nt8 >> 1][(nt8 & 1) * 2];
                    MMA16816(acc[mt2][nt8], Ah[mt2], bh[0], bh[1]);
                    MMA16816(acc[mt2][nt8], Al[mt2], bh[0], bh[1]);
                    MMA16816(acc[mt2][nt8], Ah[mt2], bl[0], bl[1]);
                }
        }
    };

    load_stage(0, 0);
    for (int kc = 0; kc < NKC; ++kc) {
        if (kc + 1 < NKC) {
            load_stage(kc + 1, (kc + 1) & 1);
            CP_WAIT(1);
        } else {
            CP_WAIT(0);
        }
        __syncthreads();
        compute(kc & 1);
        __syncthreads();
    }

    // epilogue: bias + store
    const int rgrp = lane >> 2, cpair = lane & 3;
#pragma unroll
    for (int mt2 = 0; mt2 < 2; ++mt2) {
        const int mA = m0 + wm * 32 + mt2 * 16 + rgrp;
        const float biasA = g_bias[mA];
        const float biasB = g_bias[mA + 8];
#pragma unroll
        for (int nt8 = 0; nt8 < 8; ++nt8) {
            size_t col = n0 + wn * 64 + nt8 * 8 + cpair * 2;
            float2 v0 = { acc[mt2][nt8][0] + biasA, acc[mt2][nt8][1] + biasA };
            float2 v1 = { acc[mt2][nt8][2] + biasB, acc[mt2][nt8][3] + biasB };
            *(float2*)(g_C + (size_t)mA * NROW + col)       = v0;
            *(float2*)(g_C + (size_t)(mA + 8) * NROW + col) = v1;
        }
    }
}

// ---------------- 4) scan (all dirs) -----------------------------------------
__global__ void scan_kernel(const float* __restrict__ h0v)
{
    const int gwarp = (blockIdx.x * blockDim.x + threadIdx.x) >> 5;
    const int lane  = threadIdx.x & 31;
    const int n     = blockIdx.y;
    const int half  = gwarp & 1;
    const int d1i   = (gwarp >> 1) % 63;
    const int c     = (gwarp / 126) % 32;
    const int b     = gwarp / (126 * 32);
    if (b >= NB) return;

    const int delta1 = d1i - 31;
    const int delta2 = half * 32 + lane - 31;
    const bool lane_ok = (delta2 <= 31);

    const int di = (n & 4) ? 1 : -1;
    const int dj = (n & 2) ? 1 : -1;
    const int dk = (n & 1) ? 1 : -1;

    const size_t colb = (size_t)b * NSP;
    float* hbp      = g_C + (size_t)(n * 96 +  0 + c) * NROW + colb;
    const float* zp = g_C + (size_t)(n * 96 + 32 + c) * NROW + colb;
    const float* sp = g_C + (size_t)(n * 96 + 64 + c) * NROW + colb;

    float h = h0v[n * 32 + c];

    for (int m = 0; m < 32; ++m) {
        int jf = m - delta1;
        if (jf < 0) continue;
        if (jf > 31) break;
        int kf = m - delta2;
        bool act = lane_ok && (kf >= 0) && (kf <= 31);
        int i = (di > 0) ? m  : 31 - m;
        int j = (dj > 0) ? jf : 31 - jf;
        int k = (dk > 0) ? kf : 31 - kf;
        int idx = i * 1024 + j * 32 + k;
        if (act) {
            float z  = 1.f / (1.f + __expf(-zp[idx]));
            float hb = hbp[idx];
            h = z * hb + (1.f - z) * h;
            float s = 1.f / (1.f + __expf(-sp[idx]));
            hbp[idx] = h * s;
        }
    }
}

// ---------------- 5) reduce ---------------------------------------------------
__global__ void reduce_kernel(float* __restrict__ out)
{
    const int e = blockIdx.x * 256 + threadIdx.x;
    const int b = e >> 20;
    const int c = (e >> 15) & 31;
    const int spi = e & 32767;
    const size_t col = (size_t)b * NSP + spi;
    float acc = 0.f;
#pragma unroll
    for (int n = 0; n < 8; ++n)
        acc += g_C[(size_t)(n * 96 + c) * NROW + col];
    out[e] = acc;
}

// ---------------- launch -------------------------------------------------------
extern "C" void kernel_launch(void* const* d_in, const int* in_sizes, int n_in,
                              void* d_out, int out_size)
{
    const float* x   = (const float*)d_in[0];
    const float* Wh  = (const float*)d_in[1];
    const float* bh  = (const float*)d_in[2];
    const float* Wz  = (const float*)d_in[3];
    const float* bz  = (const float*)d_in[4];
    const float* Ws  = (const float*)d_in[5];
    const float* bs  = (const float*)d_in[6];
    const float* h0v = (const float*)d_in[7];
    float* out = (float*)d_out;

    cudaFuncSetAttribute(im2col_kernel, cudaFuncAttributeMaxDynamicSharedMemorySize, I2C_SMEM);
    cudaFuncSetAttribute(gemm_kernel,   cudaFuncAttributeMaxDynamicSharedMemorySize, GEMM_SMEM);

    wprep_kernel<<<MTOT, 256>>>(Wh, bh, Wz, bz, Ws, bs);
    im2col_kernel<<<2048, 256, I2C_SMEM>>>(x);
    gemm_kernel<<<dim3(6, 512), 256, GEMM_SMEM>>>();
    scan_kernel<<<dim3(1008, 8), 256>>>(h0v);
    reduce_kernel<<<8192, 256>>>(out);
}

// round 6
// speedup vs baseline: 4.3866x; 2.1552x over previous
#include <cuda_runtime.h>
#include <cuda_fp16.h>
#include <cstdint>

// ===========================================================================
// GRUConv3d, single-pass fp16 HMMA GEMM:
//  1) wprep: W -> fp16 K-major [768][864], bias[768]
//  2) im2col: x -> fp16 K-major [65536][864]  (K = ci*27 + tap)
//  3) GEMM: C[768][65536] fp32 = W * Xcol^T, bias add, sigmoid for z/s gates
//  4) scan: 8 dirs, affine-index diagonal chains, contrib -> hb plane
//  5) reduce: out = sum over dirs
// ===========================================================================

#define NB 2
#define NSP 32768
#define NROW 65536
#define KDIM 864            // 32ci * 27taps = 54 * 16
#define MTOT 768            // 8 dir * 3 gate * 32 co

__device__ __align__(16) __half g_Bh[(size_t)NROW * KDIM];
__device__ __align__(16) __half g_Wh[(size_t)MTOT * KDIM];
__device__ __align__(16) float  g_C[(size_t)MTOT * NROW];
__device__ float                g_bias[MTOT];

// ---------------- helpers ---------------------------------------------------
__device__ __forceinline__ uint32_t smem_u32(const void* p) {
    uint32_t a;
    asm("{ .reg .u64 t; cvta.to.shared.u64 t, %1; cvt.u32.u64 %0, t; }" : "=r"(a) : "l"(p));
    return a;
}
__device__ __forceinline__ void cp16(uint32_t dst, const void* src) {
    asm volatile("cp.async.cg.shared.global [%0], [%1], 16;" :: "r"(dst), "l"(src));
}
#define CP_COMMIT() asm volatile("cp.async.commit_group;" ::: "memory")
#define CP_WAIT(n)  asm volatile("cp.async.wait_group %0;" :: "n"(n) : "memory")

#define LDSM4(r, a) \
    asm volatile("ldmatrix.sync.aligned.m8n8.x4.shared.b16 {%0,%1,%2,%3}, [%4];" \
                 : "=r"((r)[0]), "=r"((r)[1]), "=r"((r)[2]), "=r"((r)[3]) : "r"(a))

#define MMA16816(c, a, b0, b1) \
    asm volatile("mma.sync.aligned.m16n8k16.row.col.f32.f16.f16.f32 " \
                 "{%0,%1,%2,%3}, {%4,%5,%6,%7}, {%8,%9}, {%0,%1,%2,%3};" \
                 : "+f"((c)[0]), "+f"((c)[1]), "+f"((c)[2]), "+f"((c)[3]) \
                 : "r"((a)[0]), "r"((a)[1]), "r"((a)[2]), "r"((a)[3]), \
                   "r"(b0), "r"(b1))

// ---------------- 1) weight prep --------------------------------------------
__global__ void wprep_kernel(const float* __restrict__ Wh, const float* __restrict__ bh,
                             const float* __restrict__ Wz, const float* __restrict__ bz,
                             const float* __restrict__ Ws, const float* __restrict__ bs)
{
    const int m = blockIdx.x;
    const int n = m / 96, r = m % 96, g = r >> 5, co = r & 31;
    const float* Wp = (g == 0) ? Wh : ((g == 1) ? Wz : Ws);
    const float* bp = (g == 0) ? bh : ((g == 1) ? bz : bs);
    if (threadIdx.x == 0) g_bias[m] = bp[n * 32 + co];
    for (int k = threadIdx.x; k < KDIM; k += blockDim.x) {
        int ci = k / 27, t = k % 27;
        g_Wh[(size_t)m * KDIM + k] =
            __float2half(Wp[((n * 32 + co) * 32 + ci) * 27 + t]);
    }
}

// ---------------- 2) im2col --------------------------------------------------
#define I2C_STRIDE 904                       // halves; 1808B row, 16B aligned
#define I2C_SMEM (32 * I2C_STRIDE * 2)
__global__ void __launch_bounds__(256)
im2col_kernel(const float* __restrict__ x)
{
    extern __shared__ __half sm2[];
    const int tid = threadIdx.x, lane = tid & 31, wi = tid >> 5;
    const int bid = blockIdx.x;
    const int b = bid >> 10, d = (bid >> 5) & 31, h = bid & 31;

    for (int k = wi; k < KDIM; k += 8) {
        int ci = k / 27, t = k % 27;
        int td = t / 9, th = (t % 9) / 3, tw = t % 3;
        int gd = d + td - 1, gh = h + th - 1, gw = lane + tw - 1;
        float v = 0.f;
        if (gd >= 0 && gd < 32 && gh >= 0 && gh < 32 && gw >= 0 && gw < 32)
            v = x[(((b * 32 + ci) * 32 + gd) * 32 + gh) * 32 + gw];
        sm2[lane * I2C_STRIDE + k] = __float2half(v);
    }
    __syncthreads();

    const size_t row0 = (size_t)b * NSP + d * 1024 + h * 32;
    const uint4* smv = (const uint4*)sm2;
    uint4* gv = (uint4*)(g_Bh + row0 * KDIM);
    const int KV = KDIM / 8;                 // 108 uint4 per row
    for (int idx = tid; idx < 32 * KV; idx += 256) {
        int w = idx / KV, kv = idx % KV;
        gv[(size_t)w * KV + kv] = smv[w * (I2C_STRIDE / 8) + kv];
    }
}

// ---------------- 3) GEMM (HMMA fp16, 128x128 tile, K chunks of 32) ----------
#define ASTR_B 80                            // 64B data in 80B stride (conflict-free)
#define REG_B_OFF 10240
#define STAGE_B 20480
#define GEMM_SMEM (2 * STAGE_B)
#define NKC (KDIM / 32)                      // 27

__global__ void __launch_bounds__(256, 2)
gemm_kernel()
{
    extern __shared__ __align__(16) char sm[];
    const int tid = threadIdx.x, lane = tid & 31, wid = tid >> 5;
    const int m0 = blockIdx.x * 128;
    const size_t n0 = (size_t)blockIdx.y * 128;
    const int wm = wid & 3, wn = wid >> 2;
    const uint32_t sbase = smem_u32(sm);

    const char* gA = (const char*)g_Wh + (size_t)m0 * (KDIM * 2);
    const char* gB = (const char*)g_Bh + n0 * (KDIM * 2);

    float acc[2][8][4];
#pragma unroll
    for (int i = 0; i < 2; ++i)
#pragma unroll
        for (int j = 0; j < 8; ++j)
#pragma unroll
            for (int q = 0; q < 4; ++q) acc[i][j][q] = 0.f;

    const int a_row = lane & 15;
    const int a_k8  = (lane >> 4) << 3;
    const int b_row = wn * 64 + (lane & 7) + ((lane >> 4) << 3);
    const int b_k8  = ((lane >> 3) & 1) << 3;

    auto load_stage = [&](int kc, int s) {
        const int koff = kc * 64;                     // bytes into K-major row
        const uint32_t st = sbase + s * STAGE_B;
        for (int i = tid; i < 512; i += 256) {
            int r = i >> 2, c = (i & 3) << 4;
            uint32_t d = st + r * ASTR_B + c;
            size_t go = (size_t)r * (KDIM * 2) + koff + c;
            cp16(d, gA + go);
            cp16(d + REG_B_OFF, gB + go);
        }
        CP_COMMIT();
    };

    auto compute = [&](int s) {
        const uint32_t st = sbase + s * STAGE_B;
#pragma unroll
        for (int ks = 0; ks < 2; ++ks) {
            uint32_t A[2][4], B[4][4];
#pragma unroll
            for (int mt2 = 0; mt2 < 2; ++mt2) {
                uint32_t a = st + (wm * 32 + mt2 * 16 + a_row) * ASTR_B
                               + (ks * 16 + a_k8) * 2;
                LDSM4(A[mt2], a);
            }
#pragma unroll
            for (int bt = 0; bt < 4; ++bt) {
                uint32_t a = st + REG_B_OFF + (b_row + bt * 16) * ASTR_B
                               + (ks * 16 + b_k8) * 2;
                LDSM4(B[bt], a);
            }
#pragma unroll
            for (int mt2 = 0; mt2 < 2; ++mt2)
#pragma unroll
                for (int nt8 = 0; nt8 < 8; ++nt8) {
                    const uint32_t* bb = &B[nt8 >> 1][(nt8 & 1) * 2];
                    MMA16816(acc[mt2][nt8], A[mt2], bb[0], bb[1]);
                }
        }
    };

    load_stage(0, 0);
    for (int kc = 0; kc < NKC; ++kc) {
        if (kc + 1 < NKC) {
            load_stage(kc + 1, (kc + 1) & 1);
            CP_WAIT(1);
        } else {
            CP_WAIT(0);
        }
        __syncthreads();
        compute(kc & 1);
        __syncthreads();
    }

    // epilogue: bias + sigmoid for z/s gates, store
    const int rgrp = lane >> 2, cpair = lane & 3;
#pragma unroll
    for (int mt2 = 0; mt2 < 2; ++mt2) {
        const int mA = m0 + wm * 32 + mt2 * 16 + rgrp;
        const bool gate = ((mA >> 5) % 3) != 0;       // same for mA and mA+8
        const float biasA = g_bias[mA];
        const float biasB = g_bias[mA + 8];
#pragma unroll
        for (int nt8 = 0; nt8 < 8; ++nt8) {
            size_t col = n0 + wn * 64 + nt8 * 8 + cpair * 2;
            float v0 = acc[mt2][nt8][0] + biasA;
            float v1 = acc[mt2][nt8][1] + biasA;
            float v2 = acc[mt2][nt8][2] + biasB;
            float v3 = acc[mt2][nt8][3] + biasB;
            if (gate) {
                v0 = 1.f / (1.f + __expf(-v0));
                v1 = 1.f / (1.f + __expf(-v1));
                v2 = 1.f / (1.f + __expf(-v2));
                v3 = 1.f / (1.f + __expf(-v3));
            }
            *(float2*)(g_C + (size_t)mA * NROW + col)       = make_float2(v0, v1);
            *(float2*)(g_C + (size_t)(mA + 8) * NROW + col) = make_float2(v2, v3);
        }
    }
}

// ---------------- 4) scan (all dirs, affine index) ---------------------------
__global__ void scan_kernel(const float* __restrict__ h0v)
{
    const int gwarp = (blockIdx.x * blockDim.x + threadIdx.x) >> 5;
    const int lane  = threadIdx.x & 31;
    const int n     = blockIdx.y;
    const int half  = gwarp & 1;
    const int d1i   = (gwarp >> 1) % 63;
    const int c     = (gwarp / 126) % 32;
    const int b     = gwarp / (126 * 32);
    if (b >= NB) return;

    const int delta1 = d1i - 31;
    const int delta2 = half * 32 + lane - 31;     // [-31, 32]
    const bool lane_ok = (delta2 <= 31);

    const int di = (n & 4) ? 1 : -1;
    const int dj = (n & 2) ? 1 : -1;
    const int dk = (n & 1) ? 1 : -1;

    // idx(m) = base + m*stride
    const int stride = di * 1024 + dj * 32 + dk;
    const int i0 = (di > 0) ? 0 : 31;
    const int j0 = (dj > 0) ? -delta1 : 31 + delta1;
    const int k0 = (dk > 0) ? -delta2 : 31 + delta2;
    const int base = i0 * 1024 + j0 * 32 + k0;

    const int mlo = (delta1 > 0) ? delta1 : 0;          // j constraint (warp-uniform)
    const int mhi = (delta1 < 0) ? 31 + delta1 : 31;

    const size_t colb = (size_t)b * NSP;
    float* hbp      = g_C + (size_t)(n * 96 +  0 + c) * NROW + colb;
    const float* zp = g_C + (size_t)(n * 96 + 32 + c) * NROW + colb;
    const float* sp = g_C + (size_t)(n * 96 + 64 + c) * NROW + colb;

    float h = h0v[n * 32 + c];

    int idx = base + mlo * stride;
    for (int m = mlo; m <= mhi; ++m, idx += stride) {
        bool act = lane_ok && ((unsigned)(m - delta2) <= 31u);
        if (act) {
            float z  = zp[idx];                  // already sigmoided
            float hb = hbp[idx];
            h = fmaf(z, hb - h, h);              // z*hb + (1-z)*h
            hbp[idx] = h * sp[idx];              // contrib (s already sigmoided)
        }
    }
}

// ---------------- 5) reduce ---------------------------------------------------
__global__ void reduce_kernel(float* __restrict__ out)
{
    const int e = blockIdx.x * 256 + threadIdx.x;
    const int b = e >> 20;
    const int c = (e >> 15) & 31;
    const int spi = e & 32767;
    const size_t col = (size_t)b * NSP + spi;
    float acc = 0.f;
#pragma unroll
    for (int n = 0; n < 8; ++n)
        acc += g_C[(size_t)(n * 96 + c) * NROW + col];
    out[e] = acc;
}

// ---------------- launch -------------------------------------------------------
extern "C" void kernel_launch(void* const* d_in, const int* in_sizes, int n_in,
                              void* d_out, int out_size)
{
    const float* x   = (const float*)d_in[0];
    const float* Wh  = (const float*)d_in[1];
    const float* bh  = (const float*)d_in[2];
    const float* Wz  = (const float*)d_in[3];
    const float* bz  = (const float*)d_in[4];
    const float* Ws  = (const float*)d_in[5];
    const float* bs  = (const float*)d_in[6];
    const float* h0v = (const float*)d_in[7];
    float* out = (float*)d_out;

    cudaFuncSetAttribute(im2col_kernel, cudaFuncAttributeMaxDynamicSharedMemorySize, I2C_SMEM);
    cudaFuncSetAttribute(gemm_kernel,   cudaFuncAttributeMaxDynamicSharedMemorySize, GEMM_SMEM);

    wprep_kernel<<<MTOT, 256>>>(Wh, bh, Wz, bz, Ws, bs);
    im2col_kernel<<<2048, 256, I2C_SMEM>>>(x);
    gemm_kernel<<<dim3(6, 512), 256, GEMM_SMEM>>>();
    scan_kernel<<<dim3(1008, 8), 256>>>(h0v);
    reduce_kernel<<<8192, 256>>>(out);
}

// round 7
// speedup vs baseline: 4.7098x; 1.0737x over previous
#include <cuda_runtime.h>
#include <cuda_fp16.h>
#include <cstdint>

// ===========================================================================
// GRUConv3d, single-pass fp16 HMMA GEMM (3-stage cp.async pipeline):
//  1) wprep: W -> fp16 K-major [768][864], bias[768]
//  2) im2col: x -> fp16 K-major [65536][864]  (K = ci*27 + tap)
//  3) GEMM: C[768][65536] fp32 = W * Xcol^T, bias add, sigmoid for z/s gates
//  4) scan: 8 dirs, affine-index diagonal chains, software-pipelined loads
//  5) reduce: out = sum over dirs (float4)
// ===========================================================================

#define NB 2
#define NSP 32768
#define NROW 65536
#define KDIM 864            // 32ci * 27taps = 54 * 16
#define MTOT 768            // 8 dir * 3 gate * 32 co

__device__ __align__(16) __half g_Bh[(size_t)NROW * KDIM];
__device__ __align__(16) __half g_Wh[(size_t)MTOT * KDIM];
__device__ __align__(16) float  g_C[(size_t)MTOT * NROW];
__device__ float                g_bias[MTOT];

// ---------------- helpers ---------------------------------------------------
__device__ __forceinline__ uint32_t smem_u32(const void* p) {
    uint32_t a;
    asm("{ .reg .u64 t; cvta.to.shared.u64 t, %1; cvt.u32.u64 %0, t; }" : "=r"(a) : "l"(p));
    return a;
}
__device__ __forceinline__ void cp16(uint32_t dst, const void* src) {
    asm volatile("cp.async.cg.shared.global [%0], [%1], 16;" :: "r"(dst), "l"(src));
}
#define CP_COMMIT() asm volatile("cp.async.commit_group;" ::: "memory")
#define CP_WAIT(n)  asm volatile("cp.async.wait_group %0;" :: "n"(n) : "memory")

#define LDSM4(r, a) \
    asm volatile("ldmatrix.sync.aligned.m8n8.x4.shared.b16 {%0,%1,%2,%3}, [%4];" \
                 : "=r"((r)[0]), "=r"((r)[1]), "=r"((r)[2]), "=r"((r)[3]) : "r"(a))

#define MMA16816(c, a, b0, b1) \
    asm volatile("mma.sync.aligned.m16n8k16.row.col.f32.f16.f16.f32 " \
                 "{%0,%1,%2,%3}, {%4,%5,%6,%7}, {%8,%9}, {%0,%1,%2,%3};" \
                 : "+f"((c)[0]), "+f"((c)[1]), "+f"((c)[2]), "+f"((c)[3]) \
                 : "r"((a)[0]), "r"((a)[1]), "r"((a)[2]), "r"((a)[3]), \
                   "r"(b0), "r"(b1))

// ---------------- 1) weight prep --------------------------------------------
__global__ void wprep_kernel(const float* __restrict__ Wh, const float* __restrict__ bh,
                             const float* __restrict__ Wz, const float* __restrict__ bz,
                             const float* __restrict__ Ws, const float* __restrict__ bs)
{
    const int m = blockIdx.x;
    const int n = m / 96, r = m % 96, g = r >> 5, co = r & 31;
    const float* Wp = (g == 0) ? Wh : ((g == 1) ? Wz : Ws);
    const float* bp = (g == 0) ? bh : ((g == 1) ? bz : bs);
    if (threadIdx.x == 0) g_bias[m] = bp[n * 32 + co];
    for (int k = threadIdx.x; k < KDIM; k += blockDim.x) {
        int ci = k / 27, t = k % 27;
        g_Wh[(size_t)m * KDIM + k] =
            __float2half(Wp[((n * 32 + co) * 32 + ci) * 27 + t]);
    }
}

// ---------------- 2) im2col --------------------------------------------------
#define I2C_STRIDE 904
#define I2C_SMEM (32 * I2C_STRIDE * 2)
__global__ void __launch_bounds__(256)
im2col_kernel(const float* __restrict__ x)
{
    extern __shared__ __half sm2[];
    const int tid = threadIdx.x, lane = tid & 31, wi = tid >> 5;
    const int bid = blockIdx.x;
    const int b = bid >> 10, d = (bid >> 5) & 31, h = bid & 31;

    for (int k = wi; k < KDIM; k += 8) {
        int ci = k / 27, t = k % 27;
        int td = t / 9, th = (t % 9) / 3, tw = t % 3;
        int gd = d + td - 1, gh = h + th - 1, gw = lane + tw - 1;
        float v = 0.f;
        if (gd >= 0 && gd < 32 && gh >= 0 && gh < 32 && gw >= 0 && gw < 32)
            v = x[(((b * 32 + ci) * 32 + gd) * 32 + gh) * 32 + gw];
        sm2[lane * I2C_STRIDE + k] = __float2half(v);
    }
    __syncthreads();

    const size_t row0 = (size_t)b * NSP + d * 1024 + h * 32;
    const uint4* smv = (const uint4*)sm2;
    uint4* gv = (uint4*)(g_Bh + row0 * KDIM);
    const int KV = KDIM / 8;                 // 108
    for (int idx = tid; idx < 32 * KV; idx += 256) {
        int w = idx / KV, kv = idx % KV;
        gv[(size_t)w * KV + kv] = smv[w * (I2C_STRIDE / 8) + kv];
    }
}

// ---------------- 3) GEMM (HMMA fp16, 128x128 tile, 3-stage, K chunks of 32) -
#define ASTR_B 80
#define REG_B_OFF 10240
#define STAGE_B 20480
#define NSTG 3
#define GEMM_SMEM (NSTG * STAGE_B)
#define NKC (KDIM / 32)                      // 27

__global__ void __launch_bounds__(256, 2)
gemm_kernel()
{
    extern __shared__ __align__(16) char sm[];
    const int tid = threadIdx.x, lane = tid & 31, wid = tid >> 5;
    const int m0 = blockIdx.x * 128;
    const size_t n0 = (size_t)blockIdx.y * 128;
    const int wm = wid & 3, wn = wid >> 2;
    const uint32_t sbase = smem_u32(sm);

    const char* gA = (const char*)g_Wh + (size_t)m0 * (KDIM * 2);
    const char* gB = (const char*)g_Bh + n0 * (KDIM * 2);

    float acc[2][8][4];
#pragma unroll
    for (int i = 0; i < 2; ++i)
#pragma unroll
        for (int j = 0; j < 8; ++j)
#pragma unroll
            for (int q = 0; q < 4; ++q) acc[i][j][q] = 0.f;

    const int a_row = lane & 15;
    const int a_k8  = (lane >> 4) << 3;
    const int b_row = wn * 64 + (lane & 7) + ((lane >> 4) << 3);
    const int b_k8  = ((lane >> 3) & 1) << 3;

    auto load_stage = [&](int kc, int s) {
        const int koff = kc * 64;
        const uint32_t st = sbase + s * STAGE_B;
        for (int i = tid; i < 512; i += 256) {
            int r = i >> 2, c = (i & 3) << 4;
            uint32_t d = st + r * ASTR_B + c;
            size_t go = (size_t)r * (KDIM * 2) + koff + c;
            cp16(d, gA + go);
            cp16(d + REG_B_OFF, gB + go);
        }
        CP_COMMIT();
    };

    auto compute = [&](int s) {
        const uint32_t st = sbase + s * STAGE_B;
#pragma unroll
        for (int ks = 0; ks < 2; ++ks) {
            uint32_t A[2][4], B[4][4];
#pragma unroll
            for (int mt2 = 0; mt2 < 2; ++mt2) {
                uint32_t a = st + (wm * 32 + mt2 * 16 + a_row) * ASTR_B
                               + (ks * 16 + a_k8) * 2;
                LDSM4(A[mt2], a);
            }
#pragma unroll
            for (int bt = 0; bt < 4; ++bt) {
                uint32_t a = st + REG_B_OFF + (b_row + bt * 16) * ASTR_B
                               + (ks * 16 + b_k8) * 2;
                LDSM4(B[bt], a);
            }
#pragma unroll
            for (int mt2 = 0; mt2 < 2; ++mt2)
#pragma unroll
                for (int nt8 = 0; nt8 < 8; ++nt8) {
                    const uint32_t* bb = &B[nt8 >> 1][(nt8 & 1) * 2];
                    MMA16816(acc[mt2][nt8], A[mt2], bb[0], bb[1]);
                }
        }
    };

    // 3-stage pipeline, one barrier per chunk
    load_stage(0, 0);
    load_stage(1, 1);
    int s = 0;
    for (int kc = 0; kc < NKC; ++kc) {
        CP_WAIT(1);                 // stage kc arrived (kc+1 may be in flight)
        __syncthreads();            // everyone done computing kc-1; buffer free
        if (kc + 2 < NKC) {
            int s2 = s + 2; if (s2 >= NSTG) s2 -= NSTG;
            load_stage(kc + 2, s2); // overlaps with compute below
        }
        compute(s);
        if (++s == NSTG) s = 0;
    }

    // epilogue: bias + sigmoid for z/s gates, store
    const int rgrp = lane >> 2, cpair = lane & 3;
#pragma unroll
    for (int mt2 = 0; mt2 < 2; ++mt2) {
        const int mA = m0 + wm * 32 + mt2 * 16 + rgrp;
        const bool gate = ((mA >> 5) % 3) != 0;
        const float biasA = g_bias[mA];
        const float biasB = g_bias[mA + 8];
#pragma unroll
        for (int nt8 = 0; nt8 < 8; ++nt8) {
            size_t col = n0 + wn * 64 + nt8 * 8 + cpair * 2;
            float v0 = acc[mt2][nt8][0] + biasA;
            float v1 = acc[mt2][nt8][1] + biasA;
            float v2 = acc[mt2][nt8][2] + biasB;
            float v3 = acc[mt2][nt8][3] + biasB;
            if (gate) {
                v0 = 1.f / (1.f + __expf(-v0));
                v1 = 1.f / (1.f + __expf(-v1));
                v2 = 1.f / (1.f + __expf(-v2));
                v3 = 1.f / (1.f + __expf(-v3));
            }
            *(float2*)(g_C + (size_t)mA * NROW + col)       = make_float2(v0, v1);
            *(float2*)(g_C + (size_t)(mA + 8) * NROW + col) = make_float2(v2, v3);
        }
    }
}

// ---------------- 4) scan (all dirs, pipelined loads) ------------------------
__global__ void scan_kernel(const float* __restrict__ h0v)
{
    const int gwarp = (blockIdx.x * blockDim.x + threadIdx.x) >> 5;
    const int lane  = threadIdx.x & 31;
    const int n     = blockIdx.y;
    const int half  = gwarp & 1;
    const int d1i   = (gwarp >> 1) % 63;
    const int c     = (gwarp / 126) % 32;
    const int b     = gwarp / (126 * 32);
    if (b >= NB) return;

    const int delta1 = d1i - 31;
    const int delta2 = half * 32 + lane - 31;
    const bool lane_ok = (delta2 <= 31);

    const int di = (n & 4) ? 1 : -1;
    const int dj = (n & 2) ? 1 : -1;
    const int dk = (n & 1) ? 1 : -1;

    const int stride = di * 1024 + dj * 32 + dk;
    const int i0 = (di > 0) ? 0 : 31;
    const int j0 = (dj > 0) ? -delta1 : 31 + delta1;
    const int k0 = (dk > 0) ? -delta2 : 31 + delta2;
    const int base = i0 * 1024 + j0 * 32 + k0;

    const int mlo = (delta1 > 0) ? delta1 : 0;
    const int mhi = (delta1 < 0) ? 31 + delta1 : 31;

    const size_t colb = (size_t)b * NSP;
    float* hbp      = g_C + (size_t)(n * 96 +  0 + c) * NROW + colb;
    const float* zp = g_C + (size_t)(n * 96 + 32 + c) * NROW + colb;
    const float* sp = g_C + (size_t)(n * 96 + 64 + c) * NROW + colb;

    float h = h0v[n * 32 + c];

    int idx = base + mlo * stride;
    bool act = lane_ok && ((unsigned)(mlo - delta2) <= 31u);
    float z = 0.f, hb = 0.f, s = 0.f;
    if (act) { z = zp[idx]; hb = hbp[idx]; s = sp[idx]; }

    for (int m = mlo; m <= mhi; ++m) {
        // prefetch next step's operands BEFORE the current store (breaks the
        // store->load alias serialization on hbp)
        const int nidx = idx + stride;
        const bool last = (m == mhi);
        bool nact = !last && lane_ok && ((unsigned)(m + 1 - delta2) <= 31u);
        float nz = 0.f, nhb = 0.f, ns = 0.f;
        if (nact) { nz = zp[nidx]; nhb = hbp[nidx]; ns = sp[nidx]; }

        if (act) {
            h = fmaf(z, hb - h, h);      // z*hb + (1-z)*h
            hbp[idx] = h * s;            // contrib in place of hb
        }
        idx = nidx; act = nact; z = nz; hb = nhb; s = ns;
    }
}

// ---------------- 5) reduce (float4) -----------------------------------------
__global__ void reduce_kernel(float* __restrict__ out)
{
    const int e4 = blockIdx.x * 256 + threadIdx.x;   // 2*32*32768/4 = 524288
    const int b = e4 >> 18;
    const int c = (e4 >> 13) & 31;
    const int sp4 = e4 & 8191;
    const size_t col = ((size_t)b * NSP + sp4 * 4);
    float4 acc = make_float4(0.f, 0.f, 0.f, 0.f);
#pragma unroll
    for (int n = 0; n < 8; ++n) {
        float4 v = *(const float4*)(g_C + (size_t)(n * 96 + c) * NROW + col);
        acc.x += v.x; acc.y += v.y; acc.z += v.z; acc.w += v.w;
    }
    *(float4*)(out + (((size_t)b * 32 + c) * NSP + sp4 * 4)) = acc;
}

// ---------------- launch -------------------------------------------------------
extern "C" void kernel_launch(void* const* d_in, const int* in_sizes, int n_in,
                              void* d_out, int out_size)
{
    const float* x   = (const float*)d_in[0];
    const float* Wh  = (const float*)d_in[1];
    const float* bh  = (const float*)d_in[2];
    const float* Wz  = (const float*)d_in[3];
    const float* bz  = (const float*)d_in[4];
    const float* Ws  = (const float*)d_in[5];
    const float* bs  = (const float*)d_in[6];
    const float* h0v = (const float*)d_in[7];
    float* out = (float*)d_out;

    cudaFuncSetAttribute(im2col_kernel, cudaFuncAttributeMaxDynamicSharedMemorySize, I2C_SMEM);
    cudaFuncSetAttribute(gemm_kernel,   cudaFuncAttributeMaxDynamicSharedMemorySize, GEMM_SMEM);

    wprep_kernel<<<MTOT, 256>>>(Wh, bh, Wz, bz, Ws, bs);
    im2col_kernel<<<2048, 256, I2C_SMEM>>>(x);
    gemm_kernel<<<dim3(6, 512), 256, GEMM_SMEM>>>();
    scan_kernel<<<dim3(1008, 8), 256>>>(h0v);
    reduce_kernel<<<2048, 256>>>(out);
}